// round 1
// baseline (speedup 1.0000x reference)
#include <cuda_runtime.h>
#include <math.h>
#include <stdint.h>

// Problem constants (fixed shapes for this problem)
#define N_NODES   90000
#define DIM       128
#define HID       256
#define N_EDGES   1440000
#define N_GRAPH   3000
#define NODES_PG  30
#define N_PAIRS   675000
#define BN_EPS    1e-5f

// ---------------- scratch (device globals; no allocation allowed) ----------------
__device__ float  g_agg   [N_NODES * DIM];
__device__ float  g_h     [N_NODES * HID];
__device__ float  g_h1    [N_NODES * DIM];
__device__ float  g_h2    [N_NODES * DIM];
__device__ float  g_mean  [N_NODES * DIM];
__device__ float  g_logstd[N_NODES * DIM];
__device__ float  g_z     [N_NODES * DIM];
__device__ float  g_u     [N_NODES];
__device__ float  g_v     [N_NODES];
__device__ double g_sums  [HID];
__device__ double g_sumsq [HID];
__device__ float  g_sc    [HID];
__device__ float  g_sh    [HID];
__device__ double g_kl    [1];
__device__ float  g_np    [N_GRAPH];

// ---------------- small utility kernels ----------------
__global__ void copy4_kernel(float4* __restrict__ dst, const float4* __restrict__ src, int n4) {
    int i = blockIdx.x * blockDim.x + threadIdx.x;
    if (i < n4) dst[i] = src[i];
}

__global__ void zero_stats_kernel() {
    int t = threadIdx.x;   // 256 threads
    g_sums[t]  = 0.0;
    g_sumsq[t] = 0.0;
}

__global__ void zero_misc_kernel() {
    int i = blockIdx.x * blockDim.x + threadIdx.x;
    if (i < N_GRAPH) g_np[i] = 0.0f;
    if (i == 0) g_kl[0] = 0.0;
}

// ---------------- edge aggregation: agg[dst] += x[src] (one warp per edge) ----------------
__global__ void edge_agg_kernel(const float* __restrict__ x,
                                const int* __restrict__ src,
                                const int* __restrict__ dst,
                                float* __restrict__ agg, int E) {
    int w = (blockIdx.x * blockDim.x + threadIdx.x) >> 5;
    int lane = threadIdx.x & 31;
    if (w >= E) return;
    int s = src[w];   // same address across warp -> broadcast
    int d = dst[w];
    float4 v = reinterpret_cast<const float4*>(x + (size_t)s * DIM)[lane];
    float* ad = agg + (size_t)d * DIM + lane * 4;
    atomicAdd(ad + 0, v.x);
    atomicAdd(ad + 1, v.y);
    atomicAdd(ad + 2, v.z);
    atomicAdd(ad + 3, v.w);
}

// ---------------- tiled fp32 GEMM: C = op(A) @ B + bias ----------------
// A: [M,K] row-major, B: [K,N] row-major, C: [M,N] row-major.
// If NORM: a := a*sc[k] + sh[k]   (BN affine folded into A-load)
// If RELU: a := max(a, 0)         (applied after NORM)
template<bool NORM, bool RELU>
__global__ void __launch_bounds__(256)
gemm_kernel(const float* __restrict__ A, const float* __restrict__ B,
            const float* __restrict__ bias,
            const float* __restrict__ sc, const float* __restrict__ sh,
            float* __restrict__ C, int M, int N, int K) {
    const int BM = 64, BN = 64, BK = 16;
    __shared__ float As[BK][BM + 4];
    __shared__ float Bs[BK][BN];

    int tid = threadIdx.x;            // 0..255
    int tx = tid & 15;                // 0..15  (N dir)
    int ty = tid >> 4;                // 0..15  (M dir)
    int rowC = blockIdx.y * BM + ty * 4;
    int colC = blockIdx.x * BN + tx * 4;

    // A tile load mapping: 64 rows x 16 k, one float4 along k per thread
    int arow = tid >> 2;              // 0..63
    int akc  = (tid & 3) * 4;         // 0,4,8,12
    // B tile load mapping: 16 k x 64 n, one float4 along n per thread
    int bk  = tid >> 4;               // 0..15
    int bnc = (tid & 15) * 4;         // 0..60

    float acc[4][4] = {};

    for (int k0 = 0; k0 < K; k0 += BK) {
        // ---- load A tile ----
        int gr = blockIdx.y * BM + arow;
        float4 av = make_float4(0.f, 0.f, 0.f, 0.f);
        if (gr < M) av = *reinterpret_cast<const float4*>(A + (size_t)gr * K + k0 + akc);
        if (NORM) {
            float4 s4 = *reinterpret_cast<const float4*>(sc + k0 + akc);
            float4 t4 = *reinterpret_cast<const float4*>(sh + k0 + akc);
            av.x = av.x * s4.x + t4.x;
            av.y = av.y * s4.y + t4.y;
            av.z = av.z * s4.z + t4.z;
            av.w = av.w * s4.w + t4.w;
        }
        if (RELU) {
            av.x = fmaxf(av.x, 0.f); av.y = fmaxf(av.y, 0.f);
            av.z = fmaxf(av.z, 0.f); av.w = fmaxf(av.w, 0.f);
        }
        As[akc + 0][arow] = av.x;
        As[akc + 1][arow] = av.y;
        As[akc + 2][arow] = av.z;
        As[akc + 3][arow] = av.w;

        // ---- load B tile ----
        float4 bv = *reinterpret_cast<const float4*>(B + (size_t)(k0 + bk) * N + blockIdx.x * BN + bnc);
        *reinterpret_cast<float4*>(&Bs[bk][bnc]) = bv;

        __syncthreads();

        #pragma unroll
        for (int kk = 0; kk < BK; ++kk) {
            float4 a4 = *reinterpret_cast<const float4*>(&As[kk][ty * 4]);
            float4 b4 = *reinterpret_cast<const float4*>(&Bs[kk][tx * 4]);
            acc[0][0] += a4.x * b4.x; acc[0][1] += a4.x * b4.y; acc[0][2] += a4.x * b4.z; acc[0][3] += a4.x * b4.w;
            acc[1][0] += a4.y * b4.x; acc[1][1] += a4.y * b4.y; acc[1][2] += a4.y * b4.z; acc[1][3] += a4.y * b4.w;
            acc[2][0] += a4.z * b4.x; acc[2][1] += a4.z * b4.y; acc[2][2] += a4.z * b4.z; acc[2][3] += a4.z * b4.w;
            acc[3][0] += a4.w * b4.x; acc[3][1] += a4.w * b4.y; acc[3][2] += a4.w * b4.z; acc[3][3] += a4.w * b4.w;
        }
        __syncthreads();
    }

    float4 bias4 = *reinterpret_cast<const float4*>(bias + colC);
    #pragma unroll
    for (int i = 0; i < 4; ++i) {
        if (rowC + i < M) {
            float4 o;
            o.x = acc[i][0] + bias4.x;
            o.y = acc[i][1] + bias4.y;
            o.z = acc[i][2] + bias4.z;
            o.w = acc[i][3] + bias4.w;
            *reinterpret_cast<float4*>(C + (size_t)(rowC + i) * N + colC) = o;
        }
    }
}

// ---------------- BN column stats over [N, 256] ----------------
__global__ void bn_stats_kernel(const float* __restrict__ h, int Nrows) {
    int col = threadIdx.x;   // 256 threads = one column each
    int rows_per = (Nrows + gridDim.x - 1) / gridDim.x;
    int r0 = blockIdx.x * rows_per;
    int r1 = min(r0 + rows_per, Nrows);
    float s = 0.f, q = 0.f;
    for (int r = r0; r < r1; ++r) {
        float v = h[(size_t)r * HID + col];
        s += v;
        q += v * v;
    }
    atomicAdd(&g_sums[col],  (double)s);
    atomicAdd(&g_sumsq[col], (double)q);
}

__global__ void bn_finalize_kernel(const float* __restrict__ gamma,
                                   const float* __restrict__ beta, int Nrows) {
    int c = threadIdx.x;     // 256
    double mu  = g_sums[c]  / (double)Nrows;
    double var = g_sumsq[c] / (double)Nrows - mu * mu;
    float s = gamma[c] * rsqrtf((float)var + BN_EPS);
    float t = beta[c] - (float)mu * s;
    g_sc[c] = s;
    g_sh[c] = t;
}

// ---------------- z = noise*exp(logstd) + mean, + KL accumulation ----------------
__global__ void z_kernel(const float* __restrict__ mean, const float* __restrict__ logstd,
                         const float* __restrict__ noise, float* __restrict__ z, int total) {
    __shared__ double red[256];
    double ka = 0.0;
    int stride = gridDim.x * blockDim.x;
    for (int i = blockIdx.x * blockDim.x + threadIdx.x; i < total; i += stride) {
        float m = mean[i], ls = logstd[i];
        float e = expf(ls);
        z[i] = noise[i] * e + m;
        ka += (double)(1.f + 2.f * ls - m * m - e * e);
    }
    red[threadIdx.x] = ka;
    __syncthreads();
    for (int o = 128; o > 0; o >>= 1) {
        if (threadIdx.x < o) red[threadIdx.x] += red[threadIdx.x + o];
        __syncthreads();
    }
    if (threadIdx.x == 0) atomicAdd(&g_kl[0], red[0]);
}

// ---------------- per-row dots: u = z.Wc[:128], v = z.Wc[128:], pooled num via Wn ----------------
__global__ void dots_kernel(const float* __restrict__ z, const float* __restrict__ Wn,
                            const float* __restrict__ Wc, int Nrows) {
    int w = (blockIdx.x * blockDim.x + threadIdx.x) >> 5;
    int lane = threadIdx.x & 31;
    if (w >= Nrows) return;
    float4 zv = reinterpret_cast<const float4*>(z + (size_t)w * DIM)[lane];
    float4 wn = reinterpret_cast<const float4*>(Wn)[lane];
    float4 wl = reinterpret_cast<const float4*>(Wc)[lane];
    float4 wh = reinterpret_cast<const float4*>(Wc + DIM)[lane];
    float dn = zv.x * wn.x + zv.y * wn.y + zv.z * wn.z + zv.w * wn.w;
    float du = zv.x * wl.x + zv.y * wl.y + zv.z * wl.z + zv.w * wl.w;
    float dv = zv.x * wh.x + zv.y * wh.y + zv.z * wh.z + zv.w * wh.w;
    #pragma unroll
    for (int o = 16; o > 0; o >>= 1) {
        dn += __shfl_xor_sync(0xffffffff, dn, o);
        du += __shfl_xor_sync(0xffffffff, du, o);
        dv += __shfl_xor_sync(0xffffffff, dv, o);
    }
    if (lane == 0) {
        g_u[w] = du;
        g_v[w] = dv;
        atomicAdd(&g_np[w / NODES_PG], dn * (1.0f / (float)NODES_PG));
    }
}

// ---------------- num_pred, num_loss, kl write (single block) ----------------
__global__ void num_kernel(const float* __restrict__ bridge_num, const float* __restrict__ bnb,
                           float* __restrict__ out) {
    __shared__ float red[1024];
    float acc = 0.f;
    float b0 = bnb[0];
    for (int g = threadIdx.x; g < N_GRAPH; g += blockDim.x) {
        float np = g_np[g] + b0;
        out[N_PAIRS + 2 + g] = np;
        acc += fabsf(np - bridge_num[g]);
    }
    red[threadIdx.x] = acc;
    __syncthreads();
    for (int o = 512; o > 0; o >>= 1) {
        if (threadIdx.x < o) red[threadIdx.x] += red[threadIdx.x + o];
        __syncthreads();
    }
    if (threadIdx.x == 0) {
        out[N_PAIRS + 1] = red[0] / (float)N_GRAPH;
        out[N_PAIRS] = (float)(0.5 * g_kl[0] / ((double)N_NODES * (double)N_NODES));
    }
}

// ---------------- A_pred = sigmoid(u[r0] + v[r1] + bc) ----------------
__global__ void apred_kernel(const int* __restrict__ bridge_idx, const float* __restrict__ bcb,
                             float* __restrict__ out, int P) {
    int p = blockIdx.x * blockDim.x + threadIdx.x;
    if (p >= P) return;
    int r0 = bridge_idx[p];
    int r1 = bridge_idx[P + p];
    float logit = g_u[r0] + g_v[r1] + bcb[0];
    out[p] = 1.f / (1.f + expf(-logit));
}

// ---------------- host orchestration ----------------
extern "C" void kernel_launch(void* const* d_in, const int* in_sizes, int n_in,
                              void* d_out, int out_size) {
    const float* x          = (const float*)d_in[0];
    const int*   ei         = (const int*)  d_in[1];
    // d_in[2] = batch (contiguous repeat(arange(G), 30) by construction; unused)
    const float* bridge_num = (const float*)d_in[3];
    const int*   bridge_idx = (const int*)  d_in[4];
    const float* noise      = (const float*)d_in[5];
    const float* W1s        = (const float*)d_in[6];
    const float* b1s        = (const float*)d_in[7];
    const float* gammas     = (const float*)d_in[8];
    const float* betas      = (const float*)d_in[9];
    const float* W2s        = (const float*)d_in[10];
    const float* b2s        = (const float*)d_in[11];
    const float* Wn         = (const float*)d_in[12];
    const float* bnb        = (const float*)d_in[13];
    const float* Wc         = (const float*)d_in[14];
    const float* bcb        = (const float*)d_in[15];
    float* out = (float*)d_out;

    const int* src = ei;
    const int* dst = ei + N_EDGES;

    float *p_agg, *p_h, *p_h1, *p_h2, *p_mean, *p_logstd, *p_z;
    cudaGetSymbolAddress((void**)&p_agg,    g_agg);
    cudaGetSymbolAddress((void**)&p_h,      g_h);
    cudaGetSymbolAddress((void**)&p_h1,     g_h1);
    cudaGetSymbolAddress((void**)&p_h2,     g_h2);
    cudaGetSymbolAddress((void**)&p_mean,   g_mean);
    cudaGetSymbolAddress((void**)&p_logstd, g_logstd);
    cudaGetSymbolAddress((void**)&p_z,      g_z);
    float *p_sc, *p_sh;
    cudaGetSymbolAddress((void**)&p_sc, g_sc);
    cudaGetSymbolAddress((void**)&p_sh, g_sh);

    const int n4 = N_NODES * DIM / 4;
    const int copy_blocks = (n4 + 255) / 256;
    const int edge_blocks = (N_EDGES * 32) / 256;
    const dim3 grid_g1(HID / 64, (N_NODES + 63) / 64);
    const dim3 grid_g2(DIM / 64, (N_NODES + 63) / 64);

    // one GIN layer: OUT = MLP_L(IN + sum_{j->i} IN_j)
    auto run_layer = [&](const float* IN, int L, float* OUT, bool relu, bool do_agg) {
        if (do_agg) {
            copy4_kernel<<<copy_blocks, 256>>>((float4*)p_agg, (const float4*)IN, n4);
            edge_agg_kernel<<<edge_blocks, 256>>>(IN, src, dst, p_agg, N_EDGES);
        }
        zero_stats_kernel<<<1, HID>>>();
        gemm_kernel<false, false><<<grid_g1, 256>>>(
            p_agg, W1s + (size_t)L * DIM * HID, b1s + L * HID,
            nullptr, nullptr, p_h, N_NODES, HID, DIM);
        bn_stats_kernel<<<256, HID>>>(p_h, N_NODES);
        bn_finalize_kernel<<<1, HID>>>(gammas + L * HID, betas + L * HID, N_NODES);
        if (relu) {
            gemm_kernel<true, true><<<grid_g2, 256>>>(
                p_h, W2s + (size_t)L * HID * DIM, b2s + L * DIM,
                p_sc, p_sh, OUT, N_NODES, DIM, HID);
        } else {
            gemm_kernel<true, false><<<grid_g2, 256>>>(
                p_h, W2s + (size_t)L * HID * DIM, b2s + L * DIM,
                p_sc, p_sh, OUT, N_NODES, DIM, HID);
        }
    };

    run_layer(x,    0, p_h1,     true,  true);
    run_layer(p_h1, 1, p_h2,     true,  true);
    run_layer(p_h2, 2, p_mean,   false, true);
    run_layer(p_h2, 3, p_logstd, false, false);  // reuse agg(h2) from layer 2

    zero_misc_kernel<<<(N_GRAPH + 255) / 256, 256>>>();
    z_kernel<<<2048, 256>>>(p_mean, p_logstd, noise, p_z, N_NODES * DIM);
    dots_kernel<<<(N_NODES * 32 + 255) / 256, 256>>>(p_z, Wn, Wc, N_NODES);
    num_kernel<<<1, 1024>>>(bridge_num, bnb, out);
    apred_kernel<<<(N_PAIRS + 255) / 256, 256>>>(bridge_idx, bcb, out, N_PAIRS);
}

// round 2
// speedup vs baseline: 1.3465x; 1.3465x over previous
#include <cuda_runtime.h>
#include <math.h>
#include <stdint.h>

// Problem constants (fixed shapes for this problem)
#define N_NODES   90000
#define DIM       128
#define HID       256
#define N_EDGES   1440000
#define N_GRAPH   3000
#define NODES_PG  30
#define N_PAIRS   675000
#define BN_EPS    1e-5f

// ---------------- scratch (device globals; no allocation allowed) ----------------
__device__ __align__(128) float  g_agg   [N_NODES * DIM];
__device__ __align__(128) float  g_h     [N_NODES * HID];
__device__ __align__(128) float  g_h1    [N_NODES * DIM];
__device__ __align__(128) float  g_h2    [N_NODES * DIM];
__device__ __align__(128) float  g_mean  [N_NODES * DIM];
__device__ __align__(128) float  g_logstd[N_NODES * DIM];
__device__ __align__(128) float  g_z     [N_NODES * DIM];
__device__ __align__(128) float  g_u     [N_NODES];
__device__ __align__(128) float  g_v     [N_NODES];
__device__ __align__(128) float  g_sums  [HID];
__device__ __align__(128) float  g_sumsq [HID];
__device__ __align__(128) float  g_sc    [HID];
__device__ __align__(128) float  g_sh    [HID];
__device__ double g_kl    [1];
__device__ __align__(128) float  g_np    [N_GRAPH];

// ---------------- small utility kernels ----------------
__global__ void copy4_kernel(float4* __restrict__ dst, const float4* __restrict__ src, int n4) {
    int i = blockIdx.x * blockDim.x + threadIdx.x;
    if (i < n4) dst[i] = src[i];
}

__global__ void zero_stats_kernel() {
    int t = threadIdx.x;   // 256 threads
    g_sums[t]  = 0.0f;
    g_sumsq[t] = 0.0f;
}

__global__ void zero_misc_kernel() {
    int i = blockIdx.x * blockDim.x + threadIdx.x;
    if (i < N_GRAPH) g_np[i] = 0.0f;
    if (i == 0) g_kl[0] = 0.0;
}

// ---------------- edge aggregation: agg[dst] += x[src] (one warp per edge) ----------------
__global__ void edge_agg_kernel(const float* __restrict__ x,
                                const int* __restrict__ src,
                                const int* __restrict__ dst,
                                float* __restrict__ agg, int E) {
    int w = (blockIdx.x * blockDim.x + threadIdx.x) >> 5;
    int lane = threadIdx.x & 31;
    if (w >= E) return;
    int s = src[w];   // same address across warp -> broadcast
    int d = dst[w];
    float4 v = reinterpret_cast<const float4*>(x + (size_t)s * DIM)[lane];
    float* ad = agg + (size_t)d * DIM + lane * 4;
    asm volatile("red.global.add.v4.f32 [%0], {%1, %2, %3, %4};"
                 :: "l"(ad), "f"(v.x), "f"(v.y), "f"(v.z), "f"(v.w) : "memory");
}

// ---------------- tiled fp32 GEMM: C = op(A) @ B + bias ----------------
// 128x128 block tile, 8x8 per thread, BK=8, double-buffered smem + reg prefetch.
// A: [M,K] row-major, B: [K,N] row-major, C: [M,N] row-major.
// If NORM: a := a*sc[k] + sh[k]   (BN affine folded into A-load)
// If RELU: a := max(a, 0)         (applied after NORM)
// If STATS: accumulate column sum/sumsq of C into stat_sum/stat_sq (fused BN stats)
template<bool NORM, bool RELU, bool STATS>
__global__ void __launch_bounds__(256, 2)
gemm_kernel(const float* __restrict__ A, const float* __restrict__ B,
            const float* __restrict__ bias,
            const float* __restrict__ sc, const float* __restrict__ sh,
            float* __restrict__ C,
            float* __restrict__ stat_sum, float* __restrict__ stat_sq,
            int M, int N, int K) {
    const int BM = 128, BN = 128, BK = 8;
    __shared__ float As[2][BK][BM + 4];
    __shared__ float Bs[2][BK][BN];
    __shared__ float s_sum[BN];
    __shared__ float s_sq[BN];

    int tid = threadIdx.x;            // 0..255
    int tx = tid & 15;                // 0..15  (N dir)
    int ty = tid >> 4;                // 0..15  (M dir)
    int bx = blockIdx.x, by = blockIdx.y;

    // A loader mapping: 128 rows x 8 k, one float4 along k per thread
    int m_l = tid >> 1;               // 0..127
    int kq  = (tid & 1) * 4;          // 0 or 4
    int gr  = by * BM + m_l;
    bool arow_ok = gr < M;
    const float* Aptr = A + (size_t)gr * K + kq;
    // B loader mapping: 8 k x 128 n, one float4 along n per thread
    int k_l = tid >> 5;               // 0..7
    int n_l = (tid & 31) * 4;         // 0..124
    const float* Bptr = B + (size_t)k_l * N + bx * BN + n_l;

    float acc[8][8] = {};
    float4 av, bv;

    auto ldg = [&](int t) {
        int k0 = t * BK;
        if (arow_ok) av = *reinterpret_cast<const float4*>(Aptr + k0);
        else         av = make_float4(0.f, 0.f, 0.f, 0.f);
        if (NORM) {
            float4 s4 = *reinterpret_cast<const float4*>(sc + k0 + kq);
            float4 t4 = *reinterpret_cast<const float4*>(sh + k0 + kq);
            av.x = av.x * s4.x + t4.x;
            av.y = av.y * s4.y + t4.y;
            av.z = av.z * s4.z + t4.z;
            av.w = av.w * s4.w + t4.w;
        }
        if (RELU) {
            av.x = fmaxf(av.x, 0.f); av.y = fmaxf(av.y, 0.f);
            av.z = fmaxf(av.z, 0.f); av.w = fmaxf(av.w, 0.f);
        }
        bv = *reinterpret_cast<const float4*>(Bptr + (size_t)k0 * N);
    };
    auto sts = [&](int b) {
        As[b][kq + 0][m_l] = av.x;
        As[b][kq + 1][m_l] = av.y;
        As[b][kq + 2][m_l] = av.z;
        As[b][kq + 3][m_l] = av.w;
        *reinterpret_cast<float4*>(&Bs[b][k_l][n_l]) = bv;
    };

    int T = K / BK;
    ldg(0);
    sts(0);
    __syncthreads();
    int buf = 0;

    for (int t = 0; t < T; ++t) {
        if (t + 1 < T) ldg(t + 1);
        #pragma unroll
        for (int kk = 0; kk < BK; ++kk) {
            float4 a0 = *reinterpret_cast<const float4*>(&As[buf][kk][ty * 8]);
            float4 a1 = *reinterpret_cast<const float4*>(&As[buf][kk][ty * 8 + 4]);
            float4 b0 = *reinterpret_cast<const float4*>(&Bs[buf][kk][tx * 8]);
            float4 b1 = *reinterpret_cast<const float4*>(&Bs[buf][kk][tx * 8 + 4]);
            float a[8] = {a0.x, a0.y, a0.z, a0.w, a1.x, a1.y, a1.z, a1.w};
            float b[8] = {b0.x, b0.y, b0.z, b0.w, b1.x, b1.y, b1.z, b1.w};
            #pragma unroll
            for (int i = 0; i < 8; ++i)
                #pragma unroll
                for (int j = 0; j < 8; ++j)
                    acc[i][j] += a[i] * b[j];
        }
        if (t + 1 < T) {
            sts(buf ^ 1);
            __syncthreads();
            buf ^= 1;
        }
    }

    int rowC = by * BM + ty * 8;
    int colC = bx * BN + tx * 8;
    float4 bias0 = *reinterpret_cast<const float4*>(bias + colC);
    float4 bias1 = *reinterpret_cast<const float4*>(bias + colC + 4);
    float bb[8] = {bias0.x, bias0.y, bias0.z, bias0.w, bias1.x, bias1.y, bias1.z, bias1.w};

    float cs[8] = {}, cq[8] = {};
    #pragma unroll
    for (int i = 0; i < 8; ++i) {
        if (rowC + i < M) {
            float o[8];
            #pragma unroll
            for (int j = 0; j < 8; ++j) o[j] = acc[i][j] + bb[j];
            float4 o0 = make_float4(o[0], o[1], o[2], o[3]);
            float4 o1 = make_float4(o[4], o[5], o[6], o[7]);
            float* crow = C + (size_t)(rowC + i) * N + colC;
            *reinterpret_cast<float4*>(crow) = o0;
            *reinterpret_cast<float4*>(crow + 4) = o1;
            if (STATS) {
                #pragma unroll
                for (int j = 0; j < 8; ++j) { cs[j] += o[j]; cq[j] += o[j] * o[j]; }
            }
        }
    }

    if (STATS) {
        if (tid < BN) { s_sum[tid] = 0.f; s_sq[tid] = 0.f; }
        __syncthreads();
        #pragma unroll
        for (int j = 0; j < 8; ++j) {
            atomicAdd(&s_sum[tx * 8 + j], cs[j]);
            atomicAdd(&s_sq[tx * 8 + j], cq[j]);
        }
        __syncthreads();
        if (tid < BN) {
            atomicAdd(&stat_sum[bx * BN + tid], s_sum[tid]);
            atomicAdd(&stat_sq[bx * BN + tid], s_sq[tid]);
        }
    }
}

__global__ void bn_finalize_kernel(const float* __restrict__ gamma,
                                   const float* __restrict__ beta, int Nrows) {
    int c = threadIdx.x;     // 256
    float inv_n = 1.0f / (float)Nrows;
    float mu  = g_sums[c] * inv_n;
    float var = fmaxf(g_sumsq[c] * inv_n - mu * mu, 0.0f);
    float s = gamma[c] * rsqrtf(var + BN_EPS);
    float t = beta[c] - mu * s;
    g_sc[c] = s;
    g_sh[c] = t;
}

// ---------------- z = noise*exp(logstd) + mean, + KL accumulation ----------------
__global__ void z_kernel(const float* __restrict__ mean, const float* __restrict__ logstd,
                         const float* __restrict__ noise, float* __restrict__ z, int total) {
    __shared__ double red[256];
    double ka = 0.0;
    int stride = gridDim.x * blockDim.x;
    for (int i = blockIdx.x * blockDim.x + threadIdx.x; i < total; i += stride) {
        float m = mean[i], ls = logstd[i];
        float e = expf(ls);
        z[i] = noise[i] * e + m;
        ka += (double)(1.f + 2.f * ls - m * m - e * e);
    }
    red[threadIdx.x] = ka;
    __syncthreads();
    for (int o = 128; o > 0; o >>= 1) {
        if (threadIdx.x < o) red[threadIdx.x] += red[threadIdx.x + o];
        __syncthreads();
    }
    if (threadIdx.x == 0) atomicAdd(&g_kl[0], red[0]);
}

// ---------------- per-row dots: u = z.Wc[:128], v = z.Wc[128:], pooled num via Wn ----------------
__global__ void dots_kernel(const float* __restrict__ z, const float* __restrict__ Wn,
                            const float* __restrict__ Wc, int Nrows) {
    int w = (blockIdx.x * blockDim.x + threadIdx.x) >> 5;
    int lane = threadIdx.x & 31;
    if (w >= Nrows) return;
    float4 zv = reinterpret_cast<const float4*>(z + (size_t)w * DIM)[lane];
    float4 wn = reinterpret_cast<const float4*>(Wn)[lane];
    float4 wl = reinterpret_cast<const float4*>(Wc)[lane];
    float4 wh = reinterpret_cast<const float4*>(Wc + DIM)[lane];
    float dn = zv.x * wn.x + zv.y * wn.y + zv.z * wn.z + zv.w * wn.w;
    float du = zv.x * wl.x + zv.y * wl.y + zv.z * wl.z + zv.w * wl.w;
    float dv = zv.x * wh.x + zv.y * wh.y + zv.z * wh.z + zv.w * wh.w;
    #pragma unroll
    for (int o = 16; o > 0; o >>= 1) {
        dn += __shfl_xor_sync(0xffffffff, dn, o);
        du += __shfl_xor_sync(0xffffffff, du, o);
        dv += __shfl_xor_sync(0xffffffff, dv, o);
    }
    if (lane == 0) {
        g_u[w] = du;
        g_v[w] = dv;
        atomicAdd(&g_np[w / NODES_PG], dn * (1.0f / (float)NODES_PG));
    }
}

// ---------------- num_pred, num_loss, kl write (single block) ----------------
__global__ void num_kernel(const float* __restrict__ bridge_num, const float* __restrict__ bnb,
                           float* __restrict__ out) {
    __shared__ float red[1024];
    float acc = 0.f;
    float b0 = bnb[0];
    for (int g = threadIdx.x; g < N_GRAPH; g += blockDim.x) {
        float np = g_np[g] + b0;
        out[N_PAIRS + 2 + g] = np;
        acc += fabsf(np - bridge_num[g]);
    }
    red[threadIdx.x] = acc;
    __syncthreads();
    for (int o = 512; o > 0; o >>= 1) {
        if (threadIdx.x < o) red[threadIdx.x] += red[threadIdx.x + o];
        __syncthreads();
    }
    if (threadIdx.x == 0) {
        out[N_PAIRS + 1] = red[0] / (float)N_GRAPH;
        out[N_PAIRS] = (float)(0.5 * g_kl[0] / ((double)N_NODES * (double)N_NODES));
    }
}

// ---------------- A_pred = sigmoid(u[r0] + v[r1] + bc) ----------------
__global__ void apred_kernel(const int* __restrict__ bridge_idx, const float* __restrict__ bcb,
                             float* __restrict__ out, int P) {
    int p = blockIdx.x * blockDim.x + threadIdx.x;
    if (p >= P) return;
    int r0 = bridge_idx[p];
    int r1 = bridge_idx[P + p];
    float logit = g_u[r0] + g_v[r1] + bcb[0];
    out[p] = 1.f / (1.f + expf(-logit));
}

// ---------------- host orchestration ----------------
extern "C" void kernel_launch(void* const* d_in, const int* in_sizes, int n_in,
                              void* d_out, int out_size) {
    const float* x          = (const float*)d_in[0];
    const int*   ei         = (const int*)  d_in[1];
    // d_in[2] = batch (contiguous repeat(arange(G), 30) by construction; unused)
    const float* bridge_num = (const float*)d_in[3];
    const int*   bridge_idx = (const int*)  d_in[4];
    const float* noise      = (const float*)d_in[5];
    const float* W1s        = (const float*)d_in[6];
    const float* b1s        = (const float*)d_in[7];
    const float* gammas     = (const float*)d_in[8];
    const float* betas      = (const float*)d_in[9];
    const float* W2s        = (const float*)d_in[10];
    const float* b2s        = (const float*)d_in[11];
    const float* Wn         = (const float*)d_in[12];
    const float* bnb        = (const float*)d_in[13];
    const float* Wc         = (const float*)d_in[14];
    const float* bcb        = (const float*)d_in[15];
    float* out = (float*)d_out;

    const int* src = ei;
    const int* dst = ei + N_EDGES;

    float *p_agg, *p_h, *p_h1, *p_h2, *p_mean, *p_logstd, *p_z;
    cudaGetSymbolAddress((void**)&p_agg,    g_agg);
    cudaGetSymbolAddress((void**)&p_h,      g_h);
    cudaGetSymbolAddress((void**)&p_h1,     g_h1);
    cudaGetSymbolAddress((void**)&p_h2,     g_h2);
    cudaGetSymbolAddress((void**)&p_mean,   g_mean);
    cudaGetSymbolAddress((void**)&p_logstd, g_logstd);
    cudaGetSymbolAddress((void**)&p_z,      g_z);
    float *p_sc, *p_sh, *p_sums, *p_sumsq;
    cudaGetSymbolAddress((void**)&p_sc,    g_sc);
    cudaGetSymbolAddress((void**)&p_sh,    g_sh);
    cudaGetSymbolAddress((void**)&p_sums,  g_sums);
    cudaGetSymbolAddress((void**)&p_sumsq, g_sumsq);

    const int n4 = N_NODES * DIM / 4;
    const int copy_blocks = (n4 + 255) / 256;
    const int edge_blocks = (N_EDGES * 32) / 256;
    const int mblocks = (N_NODES + 127) / 128;
    const dim3 grid_g1(HID / 128, mblocks);
    const dim3 grid_g2(DIM / 128, mblocks);

    // one GIN layer: OUT = MLP_L(IN + sum_{j->i} IN_j)
    auto run_layer = [&](const float* IN, int L, float* OUT, bool relu, bool do_agg) {
        if (do_agg) {
            copy4_kernel<<<copy_blocks, 256>>>((float4*)p_agg, (const float4*)IN, n4);
            edge_agg_kernel<<<edge_blocks, 256>>>(IN, src, dst, p_agg, N_EDGES);
        }
        zero_stats_kernel<<<1, HID>>>();
        gemm_kernel<false, false, true><<<grid_g1, 256>>>(
            p_agg, W1s + (size_t)L * DIM * HID, b1s + L * HID,
            nullptr, nullptr, p_h, p_sums, p_sumsq, N_NODES, HID, DIM);
        bn_finalize_kernel<<<1, HID>>>(gammas + L * HID, betas + L * HID, N_NODES);
        if (relu) {
            gemm_kernel<true, true, false><<<grid_g2, 256>>>(
                p_h, W2s + (size_t)L * HID * DIM, b2s + L * DIM,
                p_sc, p_sh, OUT, nullptr, nullptr, N_NODES, DIM, HID);
        } else {
            gemm_kernel<true, false, false><<<grid_g2, 256>>>(
                p_h, W2s + (size_t)L * HID * DIM, b2s + L * DIM,
                p_sc, p_sh, OUT, nullptr, nullptr, N_NODES, DIM, HID);
        }
    };

    run_layer(x,    0, p_h1,     true,  true);
    run_layer(p_h1, 1, p_h2,     true,  true);
    run_layer(p_h2, 2, p_mean,   false, true);
    run_layer(p_h2, 3, p_logstd, false, false);  // reuse agg(h2) from layer 2

    zero_misc_kernel<<<(N_GRAPH + 255) / 256, 256>>>();
    z_kernel<<<2048, 256>>>(p_mean, p_logstd, noise, p_z, N_NODES * DIM);
    dots_kernel<<<(N_NODES * 32 + 255) / 256, 256>>>(p_z, Wn, Wc, N_NODES);
    num_kernel<<<1, 1024>>>(bridge_num, bnb, out);
    apred_kernel<<<(N_PAIRS + 255) / 256, 256>>>(bridge_idx, bcb, out, N_PAIRS);
}

// round 6
// speedup vs baseline: 2.0265x; 1.5050x over previous
#include <cuda_runtime.h>
#include <math.h>
#include <stdint.h>

// Problem constants (fixed shapes for this problem)
#define N_NODES   90000
#define DIM       128
#define HID       256
#define N_EDGES   1440000
#define N_GRAPH   3000
#define NODES_PG  30
#define N_PAIRS   675000
#define BN_EPS    1e-5f

// ---------------- scratch (device globals; no allocation allowed) ----------------
__device__ __align__(128) float  g_agg   [N_NODES * DIM];
__device__ __align__(128) float  g_h     [N_NODES * HID];
__device__ __align__(128) float  g_h1    [N_NODES * DIM];
__device__ __align__(128) float  g_h2    [N_NODES * DIM];
__device__ __align__(128) float  g_mean  [N_NODES * DIM];
__device__ __align__(128) float  g_logstd[N_NODES * DIM];
__device__ __align__(128) float  g_z     [N_NODES * DIM];
__device__ __align__(128) float  g_u     [N_NODES];
__device__ __align__(128) float  g_v     [N_NODES];
__device__ __align__(128) float  g_sums  [HID];
__device__ __align__(128) float  g_sumsq [HID];
__device__ __align__(128) float  g_sc    [HID];
__device__ __align__(128) float  g_sh    [HID];
__device__ double g_kl    [1];
__device__ __align__(128) float  g_np    [N_GRAPH];

// ---------------- helpers ----------------
__device__ __forceinline__ uint32_t f2tf32(float f) {
    uint32_t r;
    asm("cvt.rna.tf32.f32 %0, %1;" : "=r"(r) : "f"(f));
    return r;
}

__device__ __forceinline__ void mma_tf32(float* d, const uint32_t* a, const uint32_t* b) {
    asm volatile(
        "mma.sync.aligned.m16n8k8.row.col.f32.tf32.tf32.f32 "
        "{%0,%1,%2,%3}, {%4,%5,%6,%7}, {%8,%9}, {%0,%1,%2,%3};"
        : "+f"(d[0]), "+f"(d[1]), "+f"(d[2]), "+f"(d[3])
        : "r"(a[0]), "r"(a[1]), "r"(a[2]), "r"(a[3]), "r"(b[0]), "r"(b[1]));
}

// ---------------- small utility kernels ----------------
__global__ void copy4_kernel(float4* __restrict__ dst, const float4* __restrict__ src, int n4) {
    int i = blockIdx.x * blockDim.x + threadIdx.x;
    if (i < n4) dst[i] = src[i];
}

__global__ void zero_stats_kernel() {
    int t = threadIdx.x;   // 256 threads
    g_sums[t]  = 0.0f;
    g_sumsq[t] = 0.0f;
}

__global__ void zero_misc_kernel() {
    int i = blockIdx.x * blockDim.x + threadIdx.x;
    if (i < N_GRAPH) g_np[i] = 0.0f;
    if (i == 0) g_kl[0] = 0.0;
}

// ---------------- edge aggregation: agg[dst] += x[src] (one warp per edge) ----------------
__global__ void edge_agg_kernel(const float* __restrict__ x,
                                const int* __restrict__ src,
                                const int* __restrict__ dst,
                                float* __restrict__ agg, int E) {
    int w = (blockIdx.x * blockDim.x + threadIdx.x) >> 5;
    int lane = threadIdx.x & 31;
    if (w >= E) return;
    int s = src[w];   // same address across warp -> broadcast
    int d = dst[w];
    float4 v = reinterpret_cast<const float4*>(x + (size_t)s * DIM)[lane];
    float* ad = agg + (size_t)d * DIM + lane * 4;
    asm volatile("red.global.add.v4.f32 [%0], {%1, %2, %3, %4};"
                 :: "l"(ad), "f"(v.x), "f"(v.y), "f"(v.z), "f"(v.w) : "memory");
}

// ---------------- tf32 mma.sync GEMM ----------------
// C[M, NT] = op(A[M, KT]) @ B[KT, NT] + bias, computed in 128x128 CTA tiles.
// op(A): if NORM a := a*sc[k]+sh[k]; if RELU a := max(a,0).
// If STATS: column sum/sumsq of C accumulated into stat_sum/stat_sq.
// grid = (NT/128, ceil(M/128)), 256 threads (8 warps: 2 in m x 4 in n, warp tile 64x32).
template<int NT, int KT, bool NORM, bool RELU, bool STATS>
__global__ void __launch_bounds__(256, 2)
gemm_mma(const float* __restrict__ A, const float* __restrict__ B,
         const float* __restrict__ bias, const float* __restrict__ sc,
         const float* __restrict__ sh, float* __restrict__ C,
         float* __restrict__ stat_sum, float* __restrict__ stat_sq, int M) {
    constexpr int T = KT / 16;
    __shared__ uint32_t As[16][132];   // [k][m], pad 4 -> fragment LDS conflict-free
    __shared__ uint32_t Bs[16][132];   // [k][n]
    __shared__ float s_sum[128];
    __shared__ float s_sq[128];

    int tid = threadIdx.x;
    int lane = tid & 31;
    int wid = tid >> 5;
    int g = lane >> 2, tig = lane & 3;
    int wm = wid >> 2;      // 0..1 (m)
    int wn = wid & 3;       // 0..3 (n)
    int bx = blockIdx.x, by = blockIdx.y;

    if (STATS && tid < 128) { s_sum[tid] = 0.f; s_sq[tid] = 0.f; }

    // A loader: f4 = tid + it*256 -> row = f4>>2, kquad = (tid&3)*4
    int ar = tid >> 2;
    int aq = (tid & 3) * 4;
    // B loader: f4 = tid + it*256 -> krow = (tid>>5)+8*it, ncol4 = (tid&31)*4
    int bkb = tid >> 5;
    int bn4 = (tid & 31) * 4;

    float4 aR[2], bR[2];
    auto LDG = [&](int t) {
        int k0 = t * 16;
        #pragma unroll
        for (int it = 0; it < 2; ++it) {
            int grow = by * 128 + ar + it * 64;
            float4 v = make_float4(0.f, 0.f, 0.f, 0.f);
            if (grow < M) v = *reinterpret_cast<const float4*>(A + (size_t)grow * KT + k0 + aq);
            if (NORM) {
                float4 s4 = *reinterpret_cast<const float4*>(sc + k0 + aq);
                float4 t4 = *reinterpret_cast<const float4*>(sh + k0 + aq);
                v.x = v.x * s4.x + t4.x;
                v.y = v.y * s4.y + t4.y;
                v.z = v.z * s4.z + t4.z;
                v.w = v.w * s4.w + t4.w;
            }
            if (RELU) {
                v.x = fmaxf(v.x, 0.f); v.y = fmaxf(v.y, 0.f);
                v.z = fmaxf(v.z, 0.f); v.w = fmaxf(v.w, 0.f);
            }
            aR[it] = v;
            int kb = bkb + it * 8;
            bR[it] = *reinterpret_cast<const float4*>(B + (size_t)(k0 + kb) * NT + bx * 128 + bn4);
        }
    };
    auto STS = [&]() {
        #pragma unroll
        for (int it = 0; it < 2; ++it) {
            int r = ar + it * 64;
            As[aq + 0][r] = f2tf32(aR[it].x);
            As[aq + 1][r] = f2tf32(aR[it].y);
            As[aq + 2][r] = f2tf32(aR[it].z);
            As[aq + 3][r] = f2tf32(aR[it].w);
            int kb = bkb + it * 8;
            Bs[kb][bn4 + 0] = f2tf32(bR[it].x);
            Bs[kb][bn4 + 1] = f2tf32(bR[it].y);
            Bs[kb][bn4 + 2] = f2tf32(bR[it].z);
            Bs[kb][bn4 + 3] = f2tf32(bR[it].w);
        }
    };

    float acc[4][4][4] = {};

    LDG(0);
    for (int t = 0; t < T; ++t) {
        if (t) __syncthreads();
        STS();
        __syncthreads();
        if (t + 1 < T) LDG(t + 1);
        #pragma unroll
        for (int c0 = 0; c0 < 16; c0 += 8) {
            uint32_t af[4][4], bf[4][2];
            #pragma unroll
            for (int i = 0; i < 4; ++i) {
                int mb = wm * 64 + i * 16 + g;
                af[i][0] = As[c0 + tig][mb];
                af[i][1] = As[c0 + tig][mb + 8];
                af[i][2] = As[c0 + tig + 4][mb];
                af[i][3] = As[c0 + tig + 4][mb + 8];
            }
            #pragma unroll
            for (int j = 0; j < 4; ++j) {
                int nb = wn * 32 + j * 8 + g;
                bf[j][0] = Bs[c0 + tig][nb];
                bf[j][1] = Bs[c0 + tig + 4][nb];
            }
            #pragma unroll
            for (int i = 0; i < 4; ++i)
                #pragma unroll
                for (int j = 0; j < 4; ++j)
                    mma_tf32(acc[i][j], af[i], bf[j]);
        }
    }

    // ---- epilogue: +bias, store, optional fused column stats ----
    #pragma unroll
    for (int j = 0; j < 4; ++j) {
        int colL = wn * 32 + j * 8 + 2 * tig;   // local col within 128-tile
        int col = bx * 128 + colL;              // col within NT
        float b0 = __ldg(bias + col);
        float b1 = __ldg(bias + col + 1);
        float cs0 = 0.f, cq0 = 0.f, cs1 = 0.f, cq1 = 0.f;
        #pragma unroll
        for (int i = 0; i < 4; ++i) {
            int r0 = by * 128 + wm * 64 + i * 16 + g;
            float v00 = acc[i][j][0] + b0, v01 = acc[i][j][1] + b1;
            float v10 = acc[i][j][2] + b0, v11 = acc[i][j][3] + b1;
            if (r0 < M) {
                *reinterpret_cast<float2*>(C + (size_t)r0 * NT + col) = make_float2(v00, v01);
                if (STATS) { cs0 += v00; cq0 += v00 * v00; cs1 += v01; cq1 += v01 * v01; }
            }
            if (r0 + 8 < M) {
                *reinterpret_cast<float2*>(C + (size_t)(r0 + 8) * NT + col) = make_float2(v10, v11);
                if (STATS) { cs0 += v10; cq0 += v10 * v10; cs1 += v11; cq1 += v11 * v11; }
            }
        }
        if (STATS) {
            atomicAdd(&s_sum[colL], cs0);
            atomicAdd(&s_sq[colL],  cq0);
            atomicAdd(&s_sum[colL + 1], cs1);
            atomicAdd(&s_sq[colL + 1],  cq1);
        }
    }
    if (STATS) {
        __syncthreads();
        if (tid < 128) {
            atomicAdd(&stat_sum[bx * 128 + tid], s_sum[tid]);
            atomicAdd(&stat_sq[bx * 128 + tid],  s_sq[tid]);
        }
    }
}

__global__ void bn_finalize_kernel(const float* __restrict__ gamma,
                                   const float* __restrict__ beta, int Nrows) {
    int c = threadIdx.x;     // 256
    float inv_n = 1.0f / (float)Nrows;
    float mu  = g_sums[c] * inv_n;
    float var = fmaxf(g_sumsq[c] * inv_n - mu * mu, 0.0f);
    float s = gamma[c] * rsqrtf(var + BN_EPS);
    float t = beta[c] - mu * s;
    g_sc[c] = s;
    g_sh[c] = t;
}

// ---------------- z = noise*exp(logstd) + mean, + KL accumulation ----------------
__global__ void z_kernel(const float* __restrict__ mean, const float* __restrict__ logstd,
                         const float* __restrict__ noise, float* __restrict__ z, int total) {
    __shared__ double red[256];
    double ka = 0.0;
    int stride = gridDim.x * blockDim.x;
    for (int i = blockIdx.x * blockDim.x + threadIdx.x; i < total; i += stride) {
        float m = mean[i], ls = logstd[i];
        float e = expf(ls);
        z[i] = noise[i] * e + m;
        ka += (double)(1.f + 2.f * ls - m * m - e * e);
    }
    red[threadIdx.x] = ka;
    __syncthreads();
    for (int o = 128; o > 0; o >>= 1) {
        if (threadIdx.x < o) red[threadIdx.x] += red[threadIdx.x + o];
        __syncthreads();
    }
    if (threadIdx.x == 0) atomicAdd(&g_kl[0], red[0]);
}

// ---------------- per-row dots: u = z.Wc[:128], v = z.Wc[128:], pooled num via Wn ----------------
__global__ void dots_kernel(const float* __restrict__ z, const float* __restrict__ Wn,
                            const float* __restrict__ Wc, int Nrows) {
    int w = (blockIdx.x * blockDim.x + threadIdx.x) >> 5;
    int lane = threadIdx.x & 31;
    if (w >= Nrows) return;
    float4 zv = reinterpret_cast<const float4*>(z + (size_t)w * DIM)[lane];
    float4 wn = reinterpret_cast<const float4*>(Wn)[lane];
    float4 wl = reinterpret_cast<const float4*>(Wc)[lane];
    float4 wh = reinterpret_cast<const float4*>(Wc + DIM)[lane];
    float dn = zv.x * wn.x + zv.y * wn.y + zv.z * wn.z + zv.w * wn.w;
    float du = zv.x * wl.x + zv.y * wl.y + zv.z * wl.z + zv.w * wl.w;
    float dv = zv.x * wh.x + zv.y * wh.y + zv.z * wh.z + zv.w * wh.w;
    #pragma unroll
    for (int o = 16; o > 0; o >>= 1) {
        dn += __shfl_xor_sync(0xffffffff, dn, o);
        du += __shfl_xor_sync(0xffffffff, du, o);
        dv += __shfl_xor_sync(0xffffffff, dv, o);
    }
    if (lane == 0) {
        g_u[w] = du;
        g_v[w] = dv;
        atomicAdd(&g_np[w / NODES_PG], dn * (1.0f / (float)NODES_PG));
    }
}

// ---------------- num_pred, num_loss, kl write (single block) ----------------
__global__ void num_kernel(const float* __restrict__ bridge_num, const float* __restrict__ bnb,
                           float* __restrict__ out) {
    __shared__ float red[1024];
    float acc = 0.f;
    float b0 = bnb[0];
    for (int g = threadIdx.x; g < N_GRAPH; g += blockDim.x) {
        float np = g_np[g] + b0;
        out[N_PAIRS + 2 + g] = np;
        acc += fabsf(np - bridge_num[g]);
    }
    red[threadIdx.x] = acc;
    __syncthreads();
    for (int o = 512; o > 0; o >>= 1) {
        if (threadIdx.x < o) red[threadIdx.x] += red[threadIdx.x + o];
        __syncthreads();
    }
    if (threadIdx.x == 0) {
        out[N_PAIRS + 1] = red[0] / (float)N_GRAPH;
        out[N_PAIRS] = (float)(0.5 * g_kl[0] / ((double)N_NODES * (double)N_NODES));
    }
}

// ---------------- A_pred = sigmoid(u[r0] + v[r1] + bc) ----------------
__global__ void apred_kernel(const int* __restrict__ bridge_idx, const float* __restrict__ bcb,
                             float* __restrict__ out, int P) {
    int p = blockIdx.x * blockDim.x + threadIdx.x;
    if (p >= P) return;
    int r0 = bridge_idx[p];
    int r1 = bridge_idx[P + p];
    float logit = g_u[r0] + g_v[r1] + bcb[0];
    out[p] = 1.f / (1.f + expf(-logit));
}

// ---------------- host orchestration ----------------
extern "C" void kernel_launch(void* const* d_in, const int* in_sizes, int n_in,
                              void* d_out, int out_size) {
    const float* x          = (const float*)d_in[0];
    const int*   ei         = (const int*)  d_in[1];
    // d_in[2] = batch (contiguous repeat(arange(G), 30) by construction; unused)
    const float* bridge_num = (const float*)d_in[3];
    const int*   bridge_idx = (const int*)  d_in[4];
    const float* noise      = (const float*)d_in[5];
    const float* W1s        = (const float*)d_in[6];
    const float* b1s        = (const float*)d_in[7];
    const float* gammas     = (const float*)d_in[8];
    const float* betas      = (const float*)d_in[9];
    const float* W2s        = (const float*)d_in[10];
    const float* b2s        = (const float*)d_in[11];
    const float* Wn         = (const float*)d_in[12];
    const float* bnb        = (const float*)d_in[13];
    const float* Wc         = (const float*)d_in[14];
    const float* bcb        = (const float*)d_in[15];
    float* out = (float*)d_out;

    const int* src = ei;
    const int* dst = ei + N_EDGES;

    float *p_agg, *p_h, *p_h1, *p_h2, *p_mean, *p_logstd, *p_z;
    cudaGetSymbolAddress((void**)&p_agg,    g_agg);
    cudaGetSymbolAddress((void**)&p_h,      g_h);
    cudaGetSymbolAddress((void**)&p_h1,     g_h1);
    cudaGetSymbolAddress((void**)&p_h2,     g_h2);
    cudaGetSymbolAddress((void**)&p_mean,   g_mean);
    cudaGetSymbolAddress((void**)&p_logstd, g_logstd);
    cudaGetSymbolAddress((void**)&p_z,      g_z);
    float *p_sc, *p_sh, *p_sums, *p_sumsq;
    cudaGetSymbolAddress((void**)&p_sc,    g_sc);
    cudaGetSymbolAddress((void**)&p_sh,    g_sh);
    cudaGetSymbolAddress((void**)&p_sums,  g_sums);
    cudaGetSymbolAddress((void**)&p_sumsq, g_sumsq);

    const int n4 = N_NODES * DIM / 4;
    const int copy_blocks = (n4 + 255) / 256;
    const int edge_blocks = (N_EDGES * 32) / 256;
    const int mtiles = (N_NODES + 127) / 128;   // 704
    const dim3 grid_g1(2, mtiles);   // NT=256
    const dim3 grid_g2(1, mtiles);   // NT=128

    // one GIN layer: OUT = MLP_L(IN + sum_{j->i} IN_j)
    auto run_layer = [&](const float* IN, int L, float* OUT, bool relu, bool do_agg) {
        if (do_agg) {
            copy4_kernel<<<copy_blocks, 256>>>((float4*)p_agg, (const float4*)IN, n4);
            edge_agg_kernel<<<edge_blocks, 256>>>(IN, src, dst, p_agg, N_EDGES);
        }
        zero_stats_kernel<<<1, HID>>>();
        gemm_mma<256, 128, false, false, true><<<grid_g1, 256>>>(
            p_agg, W1s + (size_t)L * DIM * HID, b1s + L * HID,
            nullptr, nullptr, p_h, p_sums, p_sumsq, N_NODES);
        bn_finalize_kernel<<<1, HID>>>(gammas + L * HID, betas + L * HID, N_NODES);
        if (relu) {
            gemm_mma<128, 256, true, true, false><<<grid_g2, 256>>>(
                p_h, W2s + (size_t)L * HID * DIM, b2s + L * DIM,
                p_sc, p_sh, OUT, nullptr, nullptr, N_NODES);
        } else {
            gemm_mma<128, 256, true, false, false><<<grid_g2, 256>>>(
                p_h, W2s + (size_t)L * HID * DIM, b2s + L * DIM,
                p_sc, p_sh, OUT, nullptr, nullptr, N_NODES);
        }
    };

    run_layer(x,    0, p_h1,     true,  true);
    run_layer(p_h1, 1, p_h2,     true,  true);
    run_layer(p_h2, 2, p_mean,   false, true);
    run_layer(p_h2, 3, p_logstd, false, false);  // reuse agg(h2) from layer 2

    zero_misc_kernel<<<(N_GRAPH + 255) / 256, 256>>>();
    z_kernel<<<2048, 256>>>(p_mean, p_logstd, noise, p_z, N_NODES * DIM);
    dots_kernel<<<(N_NODES * 32 + 255) / 256, 256>>>(p_z, Wn, Wc, N_NODES);
    num_kernel<<<1, 1024>>>(bridge_num, bnb, out);
    apred_kernel<<<(N_PAIRS + 255) / 256, 256>>>(bridge_idx, bcb, out, N_PAIRS);
}